// round 7
// baseline (speedup 1.0000x reference)
#include <cuda_runtime.h>
#include <cuda_bf16.h>

#define NMAX   100000
#define EMAX   640000
#define LATDIM 128
#define VEC    32          // float4 per row
#define SCAN_B 1024
#define MAXBLK 128         // max scan blocks (98 used)

// ---- scratch (__device__ globals; allocation-free rule) --------------------
__device__ float  g_bufA[(size_t)NMAX * LATDIM];
__device__ float  g_bufB[(size_t)NMAX * LATDIM];
__device__ float2 g_stats[NMAX];          // {mu, inv} per node
__device__ int    g_cnt[NMAX];            // per-row degree (hist)
__device__ int    g_rowstart[NMAX + 1];   // ABSOLUTE exclusive prefix
__device__ int    g_rank[EMAX];
__device__ uint2  g_edges[EMAX];          // row-sorted {col, val bits}
__device__ int    g_chain_val[MAXBLK + 1];
__device__ int    g_chain_flag[MAXBLK + 1];

// ---------------------------------------------------------------------------
// prep: warp per node — LN stats {mu, inv}; zero g_cnt; block 0 resets chain
// ---------------------------------------------------------------------------
__global__ void prep_kernel(const float* __restrict__ in, int n_nodes) {
    if (blockIdx.x == 0 && threadIdx.x <= MAXBLK) {
        g_chain_flag[threadIdx.x] = (threadIdx.x == 0) ? 1 : 0;
        if (threadIdx.x == 0) g_chain_val[0] = 0;
    }
    int gw   = (blockIdx.x * blockDim.x + threadIdx.x) >> 5;
    int lane = threadIdx.x & 31;
    if (gw >= n_nodes) return;

    float4 v = __ldg(reinterpret_cast<const float4*>(in) + (size_t)gw * VEC + lane);

    float s  = v.x + v.y + v.z + v.w;
    float ss = v.x * v.x + v.y * v.y + v.z * v.z + v.w * v.w;
    #pragma unroll
    for (int o = 16; o > 0; o >>= 1) {
        s  += __shfl_xor_sync(0xFFFFFFFFu, s,  o);
        ss += __shfl_xor_sync(0xFFFFFFFFu, ss, o);
    }
    if (lane == 0) {
        float mu  = s * (1.0f / LATDIM);
        float var = ss * (1.0f / LATDIM) - mu * mu;
        g_stats[gw] = make_float2(mu, rsqrtf(var + 1e-5f));
        g_cnt[gw]   = 0;
    }
}

// ---------------------------------------------------------------------------
// hist: degree count; atomic return value IS the within-row rank
// ---------------------------------------------------------------------------
__global__ void hist_kernel(const int* __restrict__ row, int n_edges) {
    int e      = blockIdx.x * blockDim.x + threadIdx.x;
    int stride = gridDim.x * blockDim.x;
    for (; e < n_edges; e += stride)
        g_rank[e] = atomicAdd(&g_cnt[row[e]], 1);
}

// ---------------------------------------------------------------------------
// chained scan: one kernel, absolute exclusive prefix into g_rowstart.
// Block b spins on its predecessor's published prefix (all 98 blocks resident).
// ---------------------------------------------------------------------------
__global__ void scan_kernel(int n_nodes) {
    __shared__ int wsum[32];
    __shared__ int s_prefix;
    int b = blockIdx.x, t = threadIdx.x, lane = t & 31, wid = t >> 5;
    int i = b * SCAN_B + t;
    int v = (i < n_nodes) ? g_cnt[i] : 0;

    // block-local inclusive scan (shuffle)
    int x = v;
    #pragma unroll
    for (int o = 1; o < 32; o <<= 1) {
        int y = __shfl_up_sync(0xFFFFFFFFu, x, o);
        if (lane >= o) x += y;
    }
    if (lane == 31) wsum[wid] = x;
    __syncthreads();
    if (wid == 0) {
        int s = wsum[lane];
        #pragma unroll
        for (int o = 1; o < 32; o <<= 1) {
            int y = __shfl_up_sync(0xFFFFFFFFu, s, o);
            if (lane >= o) s += y;
        }
        wsum[lane] = s;
    }
    __syncthreads();
    int incl  = x + (wid ? wsum[wid - 1] : 0);
    int total = wsum[31];

    // chain: wait for predecessor prefix, publish ours
    if (t == 0) {
        while (atomicAdd(&g_chain_flag[b], 0) == 0) { }
        int pre = g_chain_val[b];
        s_prefix = pre;
        g_chain_val[b + 1] = pre + total;
        __threadfence();
        atomicExch(&g_chain_flag[b + 1], 1);
    }
    __syncthreads();
    int prefix = s_prefix;

    if (i < n_nodes) g_rowstart[i] = prefix + incl - v;   // absolute exclusive
    if (i == n_nodes - 1 || (b == gridDim.x - 1 && t == SCAN_B - 1))
        g_rowstart[n_nodes] = g_chain_val[gridDim.x > b + 1 ? b + 1 : b + 1]; // publishes running total
}

// total fixup: ensure g_rowstart[n] = n_edges (last block's published sum)
__global__ void total_kernel(int n_nodes, int n_edges) {
    if (threadIdx.x == 0 && blockIdx.x == 0) g_rowstart[n_nodes] = n_edges;
}

// atomic-free scatter using precomputed ranks + absolute rowstart
__global__ void scatter_kernel(const int* __restrict__ row,
                               const int* __restrict__ col,
                               const float* __restrict__ val,
                               int n_edges) {
    int e      = blockIdx.x * blockDim.x + threadIdx.x;
    int stride = gridDim.x * blockDim.x;
    for (; e < n_edges; e += stride) {
        int r = row[e];
        g_edges[g_rowstart[r] + g_rank[e]] =
            make_uint2((unsigned)col[e], __float_as_uint(val[e]));
    }
}

// ---------------------------------------------------------------------------
// SpMM: 1 warp per row, lane owns one float4 (round-4 structure).
// LAYER 0: gather embeds, apply LN inline via g_stats; y = acc
// LAYER 1: y = acc
// LAYER 2: out = acc + y1[r] + x[r]   (x row == y2; streaming hints)
// ---------------------------------------------------------------------------
template <int LAYER>
__global__ void __launch_bounds__(256)
spmm_kernel(const float* __restrict__ x,
            float* __restrict__ y,
            const float* __restrict__ y1,
            float* __restrict__ out,
            int n_nodes) {
    int r = (blockIdx.x * blockDim.x + threadIdx.x) >> 5;
    if (r >= n_nodes) return;
    int lane = threadIdx.x & 31;

    int base = __ldg(&g_rowstart[r]);
    int deg  = __ldg(&g_rowstart[r + 1]) - base;

    const float4* x4 = reinterpret_cast<const float4*>(x);
    float4 acc = make_float4(0.f, 0.f, 0.f, 0.f);

    for (int s = 0; s < deg; s += 32) {
        int m = deg - s; if (m > 32) m = 32;
        uint2 ev = make_uint2(0u, 0u);
        if (lane < m) ev = __ldg(&g_edges[base + s + lane]);   // coalesced meta
        #pragma unroll 4
        for (int k = 0; k < m; ++k) {
            int   c = __shfl_sync(0xFFFFFFFFu, (int)ev.x, k);
            float v = __uint_as_float(__shfl_sync(0xFFFFFFFFu, (int)ev.y, k));
            float4 xv = __ldg(x4 + (size_t)c * VEC + lane);
            if (LAYER == 0) {
                float2 st = __ldg(&g_stats[c]);      // L2-hot broadcast
                float sc  = v * st.y;                // v * inv
                float smu = sc * st.x;               // v * inv * mu
                acc.x = fmaf(sc, xv.x, acc.x) - smu;
                acc.y = fmaf(sc, xv.y, acc.y) - smu;
                acc.z = fmaf(sc, xv.z, acc.z) - smu;
                acc.w = fmaf(sc, xv.w, acc.w) - smu;
            } else {
                acc.x = fmaf(v, xv.x, acc.x);
                acc.y = fmaf(v, xv.y, acc.y);
                acc.z = fmaf(v, xv.z, acc.z);
                acc.w = fmaf(v, xv.w, acc.w);
            }
        }
    }

    size_t oi = (size_t)r * VEC + lane;
    if (LAYER < 2) {
        reinterpret_cast<float4*>(y)[oi] = acc;   // stays L2-hot for next layer
    } else {
        float4 a = __ldcs(reinterpret_cast<const float4*>(y1) + oi);  // evict-first
        float4 b = __ldg(x4 + oi);                                    // y2 row: L2-hot
        acc.x += a.x + b.x; acc.y += a.y + b.y;
        acc.z += a.z + b.z; acc.w += a.w + b.w;
        __stcs(reinterpret_cast<float4*>(out) + oi, acc);             // streaming
    }
}

// ---------------------------------------------------------------------------
// Launcher
// ---------------------------------------------------------------------------
extern "C" void kernel_launch(void* const* d_in, const int* in_sizes, int n_in,
                              void* d_out, int out_size) {
    const float* embeds  = (const float*)d_in[0];
    const int*   adj_row = (const int*)d_in[1];
    const int*   adj_col = (const int*)d_in[2];
    const float* adj_val = (const float*)d_in[3];

    int n_nodes = in_sizes[0] / LATDIM;
    int n_edges = in_sizes[1];

    float* bufA = nullptr;
    float* bufB = nullptr;
    cudaGetSymbolAddress((void**)&bufA, g_bufA);
    cudaGetSymbolAddress((void**)&bufB, g_bufB);
    float* out = (float*)d_out;

    const int TPB = 256;
    int warp_blocks = (n_nodes * 32 + TPB - 1) / TPB;   // 1 warp per node
    int scan_blocks = (n_nodes + SCAN_B - 1) / SCAN_B;

    // 1) LN stats + counter/chain reset
    prep_kernel<<<warp_blocks, TPB>>>(embeds, n_nodes);
    // 2) degree histogram + ranks
    hist_kernel<<<1024, TPB>>>(adj_row, n_edges);
    // 3) single-pass chained scan -> absolute rowstart
    scan_kernel<<<scan_blocks, SCAN_B>>>(n_nodes);
    total_kernel<<<1, 32>>>(n_nodes, n_edges);
    // 4) atomic-free scatter
    scatter_kernel<<<1024, TPB>>>(adj_row, adj_col, adj_val, n_edges);

    // 5) Layer 1: y1 = A * LN(embeds)   (embeds -> bufB, LN fused)
    spmm_kernel<0><<<warp_blocks, TPB>>>(embeds, bufB, nullptr, nullptr, n_nodes);
    // 6) Layer 2: y2 = A * y1           (bufB -> bufA)
    spmm_kernel<1><<<warp_blocks, TPB>>>(bufB, bufA, nullptr, nullptr, n_nodes);
    // 7) Layer 3: out = A*y2 + y1 + y2  (gather bufA; add bufB + bufA rows)
    spmm_kernel<2><<<warp_blocks, TPB>>>(bufA, nullptr, bufB, out, n_nodes);
}

// round 8
// speedup vs baseline: 1.4348x; 1.4348x over previous
#include <cuda_runtime.h>
#include <cuda_bf16.h>

#define NMAX   100000
#define EMAX   640000
#define LATDIM 128
#define VEC    32          // float4 per row
#define SCAN_B 1024

// ---- scratch (__device__ globals; allocation-free rule) --------------------
__device__ float  g_bufA[(size_t)NMAX * LATDIM];
__device__ float  g_bufB[(size_t)NMAX * LATDIM];
__device__ float2 g_stats[NMAX];     // {mu, inv} per node
__device__ int    g_cnt[NMAX];
__device__ int    g_rowstart[NMAX];
__device__ int    g_bsum[SCAN_B];
__device__ int    g_bpref[SCAN_B];
__device__ int    g_rank[EMAX];
__device__ uint2  g_edges[EMAX];     // row-sorted {col, raw val bits}
__device__ float2 g_v1sb[EMAX];      // layer-1: {v*inv_c, v*inv_c*mu_c}

// ---------------------------------------------------------------------------
// prep: warp per node — LN stats {mu, inv}; lane0 zeroes g_cnt
// ---------------------------------------------------------------------------
__global__ void prep_kernel(const float* __restrict__ in, int n_nodes) {
    int gw   = (blockIdx.x * blockDim.x + threadIdx.x) >> 5;
    int lane = threadIdx.x & 31;
    if (gw >= n_nodes) return;

    float4 v = __ldg(reinterpret_cast<const float4*>(in) + (size_t)gw * VEC + lane);

    float s  = v.x + v.y + v.z + v.w;
    float ss = v.x * v.x + v.y * v.y + v.z * v.z + v.w * v.w;
    #pragma unroll
    for (int o = 16; o > 0; o >>= 1) {
        s  += __shfl_xor_sync(0xFFFFFFFFu, s,  o);
        ss += __shfl_xor_sync(0xFFFFFFFFu, ss, o);
    }
    if (lane == 0) {
        float mu  = s * (1.0f / LATDIM);
        float var = ss * (1.0f / LATDIM) - mu * mu;
        g_stats[gw] = make_float2(mu, rsqrtf(var + 1e-5f));
        g_cnt[gw]   = 0;
    }
}

// ---------------------------------------------------------------------------
// hist: degree count; atomic return value IS the within-row rank
// ---------------------------------------------------------------------------
__global__ void hist_kernel(const int* __restrict__ row, int n_edges) {
    int e      = blockIdx.x * blockDim.x + threadIdx.x;
    int stride = gridDim.x * blockDim.x;
    for (; e < n_edges; e += stride)
        g_rank[e] = atomicAdd(&g_cnt[row[e]], 1);
}

// warp-shuffle block scan (exclusive), emits block total
__global__ void scan1_kernel(int n_nodes) {
    __shared__ int wsum[32];
    int t = threadIdx.x, lane = t & 31, wid = t >> 5;
    int i = blockIdx.x * SCAN_B + t;
    int v = (i < n_nodes) ? g_cnt[i] : 0;

    int x = v;
    #pragma unroll
    for (int o = 1; o < 32; o <<= 1) {
        int y = __shfl_up_sync(0xFFFFFFFFu, x, o);
        if (lane >= o) x += y;
    }
    if (lane == 31) wsum[wid] = x;
    __syncthreads();
    if (wid == 0) {
        int s = wsum[lane];
        #pragma unroll
        for (int o = 1; o < 32; o <<= 1) {
            int y = __shfl_up_sync(0xFFFFFFFFu, s, o);
            if (lane >= o) s += y;
        }
        wsum[lane] = s;
    }
    __syncthreads();
    int incl = x + (wid ? wsum[wid - 1] : 0);
    if (i < n_nodes) g_rowstart[i] = incl - v;
    if (t == SCAN_B - 1) g_bsum[blockIdx.x] = incl;
}

// 128-thread scan of the (<=128) block totals
__global__ void scan2_kernel(int n_blocks) {
    __shared__ int wsum[4];
    int t = threadIdx.x, lane = t & 31, wid = t >> 5;
    int v = (t < n_blocks) ? g_bsum[t] : 0;

    int x = v;
    #pragma unroll
    for (int o = 1; o < 32; o <<= 1) {
        int y = __shfl_up_sync(0xFFFFFFFFu, x, o);
        if (lane >= o) x += y;
    }
    if (lane == 31) wsum[wid] = x;
    __syncthreads();
    int pre = 0;
    #pragma unroll
    for (int w = 0; w < 4; ++w) if (w < wid) pre += wsum[w];
    g_bpref[t] = x + pre - v;
}

// atomic-free scatter; also precomputes layer-1 LN-folded edge values
__global__ void scatter_kernel(const int* __restrict__ row,
                               const int* __restrict__ col,
                               const float* __restrict__ val,
                               int n_edges) {
    int e      = blockIdx.x * blockDim.x + threadIdx.x;
    int stride = gridDim.x * blockDim.x;
    for (; e < n_edges; e += stride) {
        int r   = row[e];
        int idx = g_rowstart[r] + g_bpref[r >> 10] + g_rank[e];
        int c   = col[e];
        float v = val[e];
        g_edges[idx] = make_uint2((unsigned)c, __float_as_uint(v));
        float2 st = __ldg(&g_stats[c]);      // L2-hot 0.8MB table
        float v1  = v * st.y;                // v * inv_c
        g_v1sb[idx] = make_float2(v1, v1 * st.x);   // {v*inv, v*inv*mu}
    }
}

// ---------------------------------------------------------------------------
// SpMM: 1 warp per row, lane owns one float4 (round-4 proven structure).
// LAYER 0: x = raw embeds; acc = Σ v1*x_raw − Σ sb  (LN folded, precomputed)
// LAYER 1: y = acc
// LAYER 2: out = acc + y1[r] + x[r]   (x row == y2; streaming hints)
// ---------------------------------------------------------------------------
template <int LAYER>
__global__ void __launch_bounds__(256)
spmm_kernel(const float* __restrict__ x,
            float* __restrict__ y,
            const float* __restrict__ y1,
            float* __restrict__ out,
            int n_nodes) {
    int r = (blockIdx.x * blockDim.x + threadIdx.x) >> 5;
    if (r >= n_nodes) return;
    int lane = threadIdx.x & 31;

    int base = g_rowstart[r] + g_bpref[r >> 10];
    int deg  = g_cnt[r];

    const float4* x4 = reinterpret_cast<const float4*>(x);
    float4 acc = make_float4(0.f, 0.f, 0.f, 0.f);
    float ssum = 0.f;                                   // LAYER 0 only

    for (int s = 0; s < deg; s += 32) {
        int m = deg - s; if (m > 32) m = 32;
        uint2  ev = make_uint2(0u, 0u);
        float2 fv = make_float2(0.f, 0.f);
        if (lane < m) {
            if (LAYER == 0) fv = __ldg(&g_v1sb[base + s + lane]);   // coalesced
            else            ev = __ldg(&g_edges[base + s + lane]);  // coalesced
            if (LAYER == 0) ev.x = __ldg(&g_edges[base + s + lane]).x;
        }
        #pragma unroll 4
        for (int k = 0; k < m; ++k) {
            int c = __shfl_sync(0xFFFFFFFFu, (int)ev.x, k);
            float v;
            if (LAYER == 0) {
                v = __shfl_sync(0xFFFFFFFFu, fv.x, k);
                ssum += __shfl_sync(0xFFFFFFFFu, fv.y, k);
            } else {
                v = __uint_as_float(__shfl_sync(0xFFFFFFFFu, (int)ev.y, k));
            }
            float4 xv = __ldg(x4 + (size_t)c * VEC + lane);
            acc.x = fmaf(v, xv.x, acc.x);
            acc.y = fmaf(v, xv.y, acc.y);
            acc.z = fmaf(v, xv.z, acc.z);
            acc.w = fmaf(v, xv.w, acc.w);
        }
    }

    if (LAYER == 0) {
        acc.x -= ssum; acc.y -= ssum; acc.z -= ssum; acc.w -= ssum;
    }

    size_t oi = (size_t)r * VEC + lane;
    if (LAYER < 2) {
        reinterpret_cast<float4*>(y)[oi] = acc;   // stays L2-hot for next layer
    } else {
        float4 a = __ldcs(reinterpret_cast<const float4*>(y1) + oi);  // evict-first
        float4 b = __ldg(x4 + oi);                                    // y2 row: L2-hot
        acc.x += a.x + b.x; acc.y += a.y + b.y;
        acc.z += a.z + b.z; acc.w += a.w + b.w;
        __stcs(reinterpret_cast<float4*>(out) + oi, acc);             // streaming
    }
}

// ---------------------------------------------------------------------------
// Launcher
// ---------------------------------------------------------------------------
extern "C" void kernel_launch(void* const* d_in, const int* in_sizes, int n_in,
                              void* d_out, int out_size) {
    const float* embeds  = (const float*)d_in[0];
    const int*   adj_row = (const int*)d_in[1];
    const int*   adj_col = (const int*)d_in[2];
    const float* adj_val = (const float*)d_in[3];

    int n_nodes = in_sizes[0] / LATDIM;
    int n_edges = in_sizes[1];

    float* bufA = nullptr;
    float* bufB = nullptr;
    cudaGetSymbolAddress((void**)&bufA, g_bufA);
    cudaGetSymbolAddress((void**)&bufB, g_bufB);
    float* out = (float*)d_out;

    const int TPB = 256;
    int warp_blocks = (n_nodes * 32 + TPB - 1) / TPB;   // 1 warp per node
    int scan_blocks = (n_nodes + SCAN_B - 1) / SCAN_B;

    // 1) LN stats + counter zeroing (reads embeds once, writes 0.8MB)
    prep_kernel<<<warp_blocks, TPB>>>(embeds, n_nodes);
    // 2-5) CSR build (two-level scan — NO cross-block serialization)
    hist_kernel<<<1024, TPB>>>(adj_row, n_edges);
    scan1_kernel<<<scan_blocks, SCAN_B>>>(n_nodes);
    scan2_kernel<<<1, 128>>>(scan_blocks);
    scatter_kernel<<<1024, TPB>>>(adj_row, adj_col, adj_val, n_edges);

    // 6) Layer 1: y1 = A * LN(embeds)  — LN folded into precomputed edge vals
    spmm_kernel<0><<<warp_blocks, TPB>>>(embeds, bufB, nullptr, nullptr, n_nodes);
    // 7) Layer 2: y2 = A * y1           (bufB -> bufA)
    spmm_kernel<1><<<warp_blocks, TPB>>>(bufB, bufA, nullptr, nullptr, n_nodes);
    // 8) Layer 3: out = A*y2 + y1 + y2  (gather bufA; add bufB + bufA rows)
    spmm_kernel<2><<<warp_blocks, TPB>>>(bufA, nullptr, bufB, out, n_nodes);
}

// round 9
// speedup vs baseline: 1.5054x; 1.0492x over previous
#include <cuda_runtime.h>
#include <cuda_bf16.h>

#define NMAX   100000
#define EMAX   640000
#define LATDIM 128
#define VEC    32          // float4 per row
#define SCAN_B 1024
#define MAXBLK 128         // >= number of scan blocks (98)

// ---- scratch (__device__ globals; allocation-free rule) --------------------
__device__ float g_bufA[(size_t)NMAX * LATDIM];
__device__ float g_bufB[(size_t)NMAX * LATDIM];
__device__ int   g_cnt[NMAX];        // per-row degree
__device__ int   g_rowstart[NMAX];   // block-local exclusive scan
__device__ int   g_bsum[MAXBLK];     // per-scan-block totals
__device__ int   g_bpref[MAXBLK];    // exclusive scan of totals
__device__ int   g_rank[EMAX];       // within-row rank of each edge
__device__ uint2 g_edges[EMAX];      // row-sorted {col, val bits}
__device__ int   g_scan_done;        // last-block counter

// ---------------------------------------------------------------------------
// LayerNorm: warp per node, lane owns one float4; lane0 zeroes g_cnt;
// thread (0,0) resets the scan done-counter (graph-replay safe: runs first).
// ---------------------------------------------------------------------------
__global__ void ln_kernel(const float* __restrict__ in, float* __restrict__ out,
                          int n_nodes) {
    if (blockIdx.x == 0 && threadIdx.x == 0) g_scan_done = 0;

    int gw   = (blockIdx.x * blockDim.x + threadIdx.x) >> 5;
    int lane = threadIdx.x & 31;
    if (gw >= n_nodes) return;

    float4 v = __ldg(reinterpret_cast<const float4*>(in) + (size_t)gw * VEC + lane);

    float s  = v.x + v.y + v.z + v.w;
    float ss = v.x * v.x + v.y * v.y + v.z * v.z + v.w * v.w;
    #pragma unroll
    for (int o = 16; o > 0; o >>= 1) {
        s  += __shfl_xor_sync(0xFFFFFFFFu, s,  o);
        ss += __shfl_xor_sync(0xFFFFFFFFu, ss, o);
    }
    float mu  = s * (1.0f / LATDIM);
    float var = ss * (1.0f / LATDIM) - mu * mu;
    float inv = rsqrtf(var + 1e-5f);

    v.x = (v.x - mu) * inv; v.y = (v.y - mu) * inv;
    v.z = (v.z - mu) * inv; v.w = (v.w - mu) * inv;

    reinterpret_cast<float4*>(out)[(size_t)gw * VEC + lane] = v;
    if (lane == 0) g_cnt[gw] = 0;
}

// ---------------------------------------------------------------------------
// hist: degree count; atomic return value IS the within-row rank
// ---------------------------------------------------------------------------
__global__ void hist_kernel(const int* __restrict__ row, int n_edges) {
    int e      = blockIdx.x * blockDim.x + threadIdx.x;
    int stride = gridDim.x * blockDim.x;
    for (; e < n_edges; e += stride)
        g_rank[e] = atomicAdd(&g_cnt[row[e]], 1);
}

// ---------------------------------------------------------------------------
// scan: block-local shuffle scan -> g_rowstart, block totals -> g_bsum.
// LAST-ARRIVING block then scans the (<=128) totals -> g_bpref.
// No cross-block spinning; single fence + atomic per block.
// ---------------------------------------------------------------------------
__global__ void scan_kernel(int n_nodes, int n_blocks) {
    __shared__ int wsum[32];
    __shared__ int wsum2[4];
    __shared__ bool s_last;
    int t = threadIdx.x, lane = t & 31, wid = t >> 5;
    int i = blockIdx.x * SCAN_B + t;
    int v = (i < n_nodes) ? g_cnt[i] : 0;

    // block-local inclusive scan
    int x = v;
    #pragma unroll
    for (int o = 1; o < 32; o <<= 1) {
        int y = __shfl_up_sync(0xFFFFFFFFu, x, o);
        if (lane >= o) x += y;
    }
    if (lane == 31) wsum[wid] = x;
    __syncthreads();
    if (wid == 0) {
        int s = wsum[lane];
        #pragma unroll
        for (int o = 1; o < 32; o <<= 1) {
            int y = __shfl_up_sync(0xFFFFFFFFu, s, o);
            if (lane >= o) s += y;
        }
        wsum[lane] = s;
    }
    __syncthreads();
    int incl = x + (wid ? wsum[wid - 1] : 0);
    if (i < n_nodes) g_rowstart[i] = incl - v;
    if (t == SCAN_B - 1) g_bsum[blockIdx.x] = incl;

    // publish, then elect the last-arriving block
    __threadfence();
    if (t == 0)
        s_last = (atomicAdd(&g_scan_done, 1) == n_blocks - 1);
    __syncthreads();

    if (s_last) {
        int bv = 0, bx = 0;
        if (t < MAXBLK) {
            bv = (t < n_blocks) ? g_bsum[t] : 0;
            bx = bv;
            #pragma unroll
            for (int o = 1; o < 32; o <<= 1) {
                int y = __shfl_up_sync(0xFFFFFFFFu, bx, o);
                if (lane >= o) bx += y;
            }
            if (lane == 31) wsum2[wid] = bx;   // wid 0..3 for t<128
        }
        __syncthreads();
        if (t < MAXBLK) {
            int pre = 0;
            #pragma unroll
            for (int w = 0; w < 4; ++w) if (w < wid) pre += wsum2[w];
            g_bpref[t] = bx + pre - bv;
        }
    }
}

// ---------------------------------------------------------------------------
// scatter: atomic-free using precomputed ranks
// ---------------------------------------------------------------------------
__global__ void scatter_kernel(const int* __restrict__ row,
                               const int* __restrict__ col,
                               const float* __restrict__ val,
                               int n_edges) {
    int e      = blockIdx.x * blockDim.x + threadIdx.x;
    int stride = gridDim.x * blockDim.x;
    for (; e < n_edges; e += stride) {
        int r = row[e];
        int idx = g_rowstart[r] + g_bpref[r >> 10] + g_rank[e];
        g_edges[idx] = make_uint2((unsigned)col[e], __float_as_uint(val[e]));
    }
}

// ---------------------------------------------------------------------------
// SpMM (round-4 proven structure, untouched): 1 warp per row, lane owns one
// float4. Coalesced 32-edge metadata load + shuffle broadcast; register acc.
// FINAL==0 : y = acc                    (layers 1,2 — zero `out` traffic)
// FINAL==1 : out = acc + y1[r] + x[r]   (layer 3; x row == y2; streaming hints)
// ---------------------------------------------------------------------------
template <int FINAL>
__global__ void __launch_bounds__(256)
spmm_kernel(const float* __restrict__ x,
            float* __restrict__ y,
            const float* __restrict__ y1,
            float* __restrict__ out,
            int n_nodes) {
    int r = (blockIdx.x * blockDim.x + threadIdx.x) >> 5;
    if (r >= n_nodes) return;
    int lane = threadIdx.x & 31;

    int base = g_rowstart[r] + g_bpref[r >> 10];
    int deg  = g_cnt[r];

    const float4* x4 = reinterpret_cast<const float4*>(x);
    float4 acc = make_float4(0.f, 0.f, 0.f, 0.f);

    for (int s = 0; s < deg; s += 32) {
        int m = deg - s; if (m > 32) m = 32;
        uint2 ev = make_uint2(0u, 0u);
        if (lane < m) ev = __ldg(&g_edges[base + s + lane]);   // coalesced meta
        #pragma unroll 4
        for (int k = 0; k < m; ++k) {
            int   c = __shfl_sync(0xFFFFFFFFu, (int)ev.x, k);
            float v = __uint_as_float(__shfl_sync(0xFFFFFFFFu, (int)ev.y, k));
            float4 xv = __ldg(x4 + (size_t)c * VEC + lane);
            acc.x = fmaf(v, xv.x, acc.x);
            acc.y = fmaf(v, xv.y, acc.y);
            acc.z = fmaf(v, xv.z, acc.z);
            acc.w = fmaf(v, xv.w, acc.w);
        }
    }

    size_t oi = (size_t)r * VEC + lane;
    if (FINAL == 0) {
        reinterpret_cast<float4*>(y)[oi] = acc;   // stays L2-hot for next layer
    } else {
        float4 a = __ldcs(reinterpret_cast<const float4*>(y1) + oi);  // evict-first
        float4 b = __ldg(x4 + oi);                                    // y2 row: L2-hot
        acc.x += a.x + b.x; acc.y += a.y + b.y;
        acc.z += a.z + b.z; acc.w += a.w + b.w;
        __stcs(reinterpret_cast<float4*>(out) + oi, acc);             // streaming
    }
}

// ---------------------------------------------------------------------------
// Launcher
// ---------------------------------------------------------------------------
extern "C" void kernel_launch(void* const* d_in, const int* in_sizes, int n_in,
                              void* d_out, int out_size) {
    const float* embeds  = (const float*)d_in[0];
    const int*   adj_row = (const int*)d_in[1];
    const int*   adj_col = (const int*)d_in[2];
    const float* adj_val = (const float*)d_in[3];

    int n_nodes = in_sizes[0] / LATDIM;
    int n_edges = in_sizes[1];

    float* bufA = nullptr;
    float* bufB = nullptr;
    cudaGetSymbolAddress((void**)&bufA, g_bufA);
    cudaGetSymbolAddress((void**)&bufB, g_bufB);
    float* out = (float*)d_out;

    const int TPB = 256;
    int warp_blocks = (n_nodes * 32 + TPB - 1) / TPB;   // 1 warp per node
    int scan_blocks = (n_nodes + SCAN_B - 1) / SCAN_B;  // 98

    // 1) LayerNorm (embeds -> bufA) + counter zeroing + done-counter reset
    ln_kernel<<<warp_blocks, TPB>>>(embeds, bufA, n_nodes);
    // 2) degree histogram + within-row ranks
    hist_kernel<<<1024, TPB>>>(adj_row, n_edges);
    // 3) fused two-level scan (last-block pattern)
    scan_kernel<<<scan_blocks, SCAN_B>>>(n_nodes, scan_blocks);
    // 4) atomic-free scatter
    scatter_kernel<<<1024, TPB>>>(adj_row, adj_col, adj_val, n_edges);

    // 5) Layer 1: y1 = A * x0          (bufA -> bufB)
    spmm_kernel<0><<<warp_blocks, TPB>>>(bufA, bufB, nullptr, nullptr, n_nodes);
    // 6) Layer 2: y2 = A * y1          (bufB -> bufA)
    spmm_kernel<0><<<warp_blocks, TPB>>>(bufB, bufA, nullptr, nullptr, n_nodes);
    // 7) Layer 3: out = A*y2 + y1 + y2 (gather bufA; add bufB + bufA rows)
    spmm_kernel<1><<<warp_blocks, TPB>>>(bufA, nullptr, bufB, out, n_nodes);
}

// round 10
// speedup vs baseline: 1.5060x; 1.0004x over previous
#include <cuda_runtime.h>
#include <cuda_bf16.h>

#define NMAX   100000
#define EMAX   640000
#define LATDIM 128
#define VEC    32          // float4 per row
#define SCAN_B 1024
#define MAXBLK 128         // >= number of scan blocks (98)

// ---- scratch (__device__ globals; allocation-free rule) --------------------
__device__ float g_bufA[(size_t)NMAX * LATDIM];
__device__ float g_bufB[(size_t)NMAX * LATDIM];
__device__ int   g_cnt[NMAX];        // per-row degree
__device__ int   g_rowstart[NMAX];   // block-local exclusive scan
__device__ int   g_bsum[MAXBLK];     // per-scan-block totals
__device__ int   g_bpref[MAXBLK];    // exclusive scan of totals
__device__ int   g_rank[EMAX];       // within-row rank of each edge
__device__ uint2 g_edges[EMAX];      // row-sorted {col, val bits}
__device__ int   g_scan_done;        // last-block counter

// ---------------------------------------------------------------------------
// LayerNorm: warp per node, lane owns one float4; lane0 zeroes g_cnt;
// thread (0,0) resets the scan done-counter.
// ---------------------------------------------------------------------------
__global__ void ln_kernel(const float* __restrict__ in, float* __restrict__ out,
                          int n_nodes) {
    if (blockIdx.x == 0 && threadIdx.x == 0) g_scan_done = 0;

    int gw   = (blockIdx.x * blockDim.x + threadIdx.x) >> 5;
    int lane = threadIdx.x & 31;
    if (gw >= n_nodes) return;

    float4 v = __ldg(reinterpret_cast<const float4*>(in) + (size_t)gw * VEC + lane);

    float s  = v.x + v.y + v.z + v.w;
    float ss = v.x * v.x + v.y * v.y + v.z * v.z + v.w * v.w;
    #pragma unroll
    for (int o = 16; o > 0; o >>= 1) {
        s  += __shfl_xor_sync(0xFFFFFFFFu, s,  o);
        ss += __shfl_xor_sync(0xFFFFFFFFu, ss, o);
    }
    float mu  = s * (1.0f / LATDIM);
    float var = ss * (1.0f / LATDIM) - mu * mu;
    float inv = rsqrtf(var + 1e-5f);

    v.x = (v.x - mu) * inv; v.y = (v.y - mu) * inv;
    v.z = (v.z - mu) * inv; v.w = (v.w - mu) * inv;

    reinterpret_cast<float4*>(out)[(size_t)gw * VEC + lane] = v;
    if (lane == 0) g_cnt[gw] = 0;
}

// ---------------------------------------------------------------------------
// hist: ONE edge per thread; atomic return value IS the within-row rank
// ---------------------------------------------------------------------------
__global__ void hist_kernel(const int* __restrict__ row, int n_edges) {
    int e = blockIdx.x * blockDim.x + threadIdx.x;
    if (e < n_edges)
        g_rank[e] = atomicAdd(&g_cnt[row[e]], 1);
}

// ---------------------------------------------------------------------------
// scan: block-local shuffle scan -> g_rowstart, block totals -> g_bsum.
// LAST-ARRIVING block scans the (<=128) totals -> g_bpref.
// ---------------------------------------------------------------------------
__global__ void scan_kernel(int n_nodes, int n_blocks) {
    __shared__ int wsum[32];
    __shared__ int wsum2[4];
    __shared__ bool s_last;
    int t = threadIdx.x, lane = t & 31, wid = t >> 5;
    int i = blockIdx.x * SCAN_B + t;
    int v = (i < n_nodes) ? g_cnt[i] : 0;

    int x = v;
    #pragma unroll
    for (int o = 1; o < 32; o <<= 1) {
        int y = __shfl_up_sync(0xFFFFFFFFu, x, o);
        if (lane >= o) x += y;
    }
    if (lane == 31) wsum[wid] = x;
    __syncthreads();
    if (wid == 0) {
        int s = wsum[lane];
        #pragma unroll
        for (int o = 1; o < 32; o <<= 1) {
            int y = __shfl_up_sync(0xFFFFFFFFu, s, o);
            if (lane >= o) s += y;
        }
        wsum[lane] = s;
    }
    __syncthreads();
    int incl = x + (wid ? wsum[wid - 1] : 0);
    if (i < n_nodes) g_rowstart[i] = incl - v;
    if (t == SCAN_B - 1) g_bsum[blockIdx.x] = incl;

    __threadfence();
    if (t == 0)
        s_last = (atomicAdd(&g_scan_done, 1) == n_blocks - 1);
    __syncthreads();

    if (s_last) {
        int bv = 0, bx = 0;
        if (t < MAXBLK) {
            bv = (t < n_blocks) ? g_bsum[t] : 0;
            bx = bv;
            #pragma unroll
            for (int o = 1; o < 32; o <<= 1) {
                int y = __shfl_up_sync(0xFFFFFFFFu, bx, o);
                if (lane >= o) bx += y;
            }
            if (lane == 31) wsum2[wid] = bx;
        }
        __syncthreads();
        if (t < MAXBLK) {
            int pre = 0;
            #pragma unroll
            for (int w = 0; w < 4; ++w) if (w < wid) pre += wsum2[w];
            g_bpref[t] = bx + pre - bv;
        }
    }
}

// ---------------------------------------------------------------------------
// scatter: ONE edge per thread, atomic-free. All independent loads issued
// up front; only the rowstart lookup depends on row[e].
// ---------------------------------------------------------------------------
__global__ void scatter_kernel(const int* __restrict__ row,
                               const int* __restrict__ col,
                               const float* __restrict__ val,
                               int n_edges) {
    int e = blockIdx.x * blockDim.x + threadIdx.x;
    if (e >= n_edges) return;

    int   r  = __ldg(row + e);      // independent
    int   c  = __ldg(col + e);      // independent
    float v  = __ldg(val + e);      // independent
    int   rk = __ldg(&g_rank[e]);   // independent

    int base = __ldg(&g_rowstart[r]) + __ldg(&g_bpref[r >> 10]);
    g_edges[base + rk] = make_uint2((unsigned)c, __float_as_uint(v));
}

// ---------------------------------------------------------------------------
// SpMM (round-4 proven structure, untouched): 1 warp per row, lane owns one
// float4. Coalesced 32-edge metadata load + shuffle broadcast; register acc.
// FINAL==0 : y = acc                    (layers 1,2 — zero `out` traffic)
// FINAL==1 : out = acc + y1[r] + x[r]   (layer 3; x row == y2; streaming hints)
// ---------------------------------------------------------------------------
template <int FINAL>
__global__ void __launch_bounds__(256)
spmm_kernel(const float* __restrict__ x,
            float* __restrict__ y,
            const float* __restrict__ y1,
            float* __restrict__ out,
            int n_nodes) {
    int r = (blockIdx.x * blockDim.x + threadIdx.x) >> 5;
    if (r >= n_nodes) return;
    int lane = threadIdx.x & 31;

    int base = g_rowstart[r] + g_bpref[r >> 10];
    int deg  = g_cnt[r];

    const float4* x4 = reinterpret_cast<const float4*>(x);
    float4 acc = make_float4(0.f, 0.f, 0.f, 0.f);

    for (int s = 0; s < deg; s += 32) {
        int m = deg - s; if (m > 32) m = 32;
        uint2 ev = make_uint2(0u, 0u);
        if (lane < m) ev = __ldg(&g_edges[base + s + lane]);   // coalesced meta
        #pragma unroll 4
        for (int k = 0; k < m; ++k) {
            int   c = __shfl_sync(0xFFFFFFFFu, (int)ev.x, k);
            float v = __uint_as_float(__shfl_sync(0xFFFFFFFFu, (int)ev.y, k));
            float4 xv = __ldg(x4 + (size_t)c * VEC + lane);
            acc.x = fmaf(v, xv.x, acc.x);
            acc.y = fmaf(v, xv.y, acc.y);
            acc.z = fmaf(v, xv.z, acc.z);
            acc.w = fmaf(v, xv.w, acc.w);
        }
    }

    size_t oi = (size_t)r * VEC + lane;
    if (FINAL == 0) {
        reinterpret_cast<float4*>(y)[oi] = acc;   // stays L2-hot for next layer
    } else {
        float4 a = __ldcs(reinterpret_cast<const float4*>(y1) + oi);  // evict-first
        float4 b = __ldg(x4 + oi);                                    // y2 row: L2-hot
        acc.x += a.x + b.x; acc.y += a.y + b.y;
        acc.z += a.z + b.z; acc.w += a.w + b.w;
        __stcs(reinterpret_cast<float4*>(out) + oi, acc);             // streaming
    }
}

// ---------------------------------------------------------------------------
// Launcher
// ---------------------------------------------------------------------------
extern "C" void kernel_launch(void* const* d_in, const int* in_sizes, int n_in,
                              void* d_out, int out_size) {
    const float* embeds  = (const float*)d_in[0];
    const int*   adj_row = (const int*)d_in[1];
    const int*   adj_col = (const int*)d_in[2];
    const float* adj_val = (const float*)d_in[3];

    int n_nodes = in_sizes[0] / LATDIM;
    int n_edges = in_sizes[1];

    float* bufA = nullptr;
    float* bufB = nullptr;
    cudaGetSymbolAddress((void**)&bufA, g_bufA);
    cudaGetSymbolAddress((void**)&bufB, g_bufB);
    float* out = (float*)d_out;

    const int TPB = 256;
    int warp_blocks = (n_nodes * 32 + TPB - 1) / TPB;   // 1 warp per node
    int scan_blocks = (n_nodes + SCAN_B - 1) / SCAN_B;  // 98
    int edge_blocks = (n_edges + TPB - 1) / TPB;        // 1 thread per edge

    // 1) LayerNorm (embeds -> bufA) + counter zeroing + done-counter reset
    ln_kernel<<<warp_blocks, TPB>>>(embeds, bufA, n_nodes);
    // 2) degree histogram + within-row ranks (1 thread/edge)
    hist_kernel<<<edge_blocks, TPB>>>(adj_row, n_edges);
    // 3) fused two-level scan (last-block pattern)
    scan_kernel<<<scan_blocks, SCAN_B>>>(n_nodes, scan_blocks);
    // 4) atomic-free scatter (1 thread/edge, hoisted loads)
    scatter_kernel<<<edge_blocks, TPB>>>(adj_row, adj_col, adj_val, n_edges);

    // 5) Layer 1: y1 = A * x0          (bufA -> bufB)
    spmm_kernel<0><<<warp_blocks, TPB>>>(bufA, bufB, nullptr, nullptr, n_nodes);
    // 6) Layer 2: y2 = A * y1          (bufB -> bufA)
    spmm_kernel<0><<<warp_blocks, TPB>>>(bufB, bufA, nullptr, nullptr, n_nodes);
    // 7) Layer 3: out = A*y2 + y1 + y2 (gather bufA; add bufB + bufA rows)
    spmm_kernel<1><<<warp_blocks, TPB>>>(bufA, nullptr, bufB, out, n_nodes);
}

// round 11
// speedup vs baseline: 1.6381x; 1.0878x over previous
#include <cuda_runtime.h>
#include <cuda_bf16.h>

#define NMAX   100000
#define EMAX   640000
#define LATDIM 128
#define VEC    32          // float4 per row
#define SCAN_B 1024
#define MAXBLK 128         // >= number of scan blocks (98)

// ---- scratch (__device__ globals; allocation-free rule) --------------------
__device__ float g_bufA[(size_t)NMAX * LATDIM];
__device__ float g_bufB[(size_t)NMAX * LATDIM];
__device__ int   g_cnt[NMAX];          // per-row degree
__device__ int   g_rowstart[NMAX];     // block-local exclusive scan
__device__ int   g_rowabs[NMAX + 1];   // ABSOLUTE row starts (scatter fixup)
__device__ int   g_bsum[MAXBLK];       // per-scan-block totals
__device__ int   g_bpref[MAXBLK];      // exclusive scan of totals
__device__ int   g_rank[EMAX];         // within-row rank of each edge
__device__ uint2 g_edges[EMAX];        // row-sorted {col, val bits}
__device__ int   g_scan_done;          // last-block counter

// ---------------------------------------------------------------------------
// LN body: one warp per node (1024-thread blocks => 32 nodes/block)
// ---------------------------------------------------------------------------
__device__ __forceinline__ void ln_node(const float* __restrict__ in,
                                        float* __restrict__ out,
                                        int node, int lane) {
    float4 v = __ldg(reinterpret_cast<const float4*>(in) + (size_t)node * VEC + lane);

    float s  = v.x + v.y + v.z + v.w;
    float ss = v.x * v.x + v.y * v.y + v.z * v.z + v.w * v.w;
    #pragma unroll
    for (int o = 16; o > 0; o >>= 1) {
        s  += __shfl_xor_sync(0xFFFFFFFFu, s,  o);
        ss += __shfl_xor_sync(0xFFFFFFFFu, ss, o);
    }
    float mu  = s * (1.0f / LATDIM);
    float var = ss * (1.0f / LATDIM) - mu * mu;
    float inv = rsqrtf(var + 1e-5f);

    v.x = (v.x - mu) * inv; v.y = (v.y - mu) * inv;
    v.z = (v.z - mu) * inv; v.w = (v.w - mu) * inv;

    reinterpret_cast<float4*>(out)[(size_t)node * VEC + lane] = v;
}

// ---------------------------------------------------------------------------
// k0: zero counters + reset scan election counter
// ---------------------------------------------------------------------------
__global__ void zero_kernel(int n_nodes) {
    int i = blockIdx.x * blockDim.x + threadIdx.x;
    if (i == 0) g_scan_done = 0;
    if (i < n_nodes) g_cnt[i] = 0;
}

// ---------------------------------------------------------------------------
// k1: hist — one edge/thread; atomic return value IS the within-row rank
// ---------------------------------------------------------------------------
__global__ void hist_kernel(const int* __restrict__ row, int n_edges) {
    int e = blockIdx.x * blockDim.x + threadIdx.x;
    if (e < n_edges)
        g_rank[e] = atomicAdd(&g_cnt[row[e]], 1);
}

// ---------------------------------------------------------------------------
// k2: scan blocks [0, scan_blocks) + LN chunk blocks [scan_blocks, ...)
// scan: block-local shuffle scan -> g_rowstart, totals -> g_bsum;
// last-arriving scan block scans the totals -> g_bpref.
// ---------------------------------------------------------------------------
__global__ void __launch_bounds__(SCAN_B)
scan_ln_kernel(const float* __restrict__ ln_in, float* __restrict__ ln_out,
               int n_nodes, int scan_blocks, int ln_node_base) {
    int t = threadIdx.x, lane = t & 31, wid = t >> 5;

    if (blockIdx.x >= scan_blocks) {
        // --- LN chunk ---
        int node = ln_node_base + (blockIdx.x - scan_blocks) * (SCAN_B / 32) + wid;
        if (node < n_nodes) ln_node(ln_in, ln_out, node, lane);
        return;
    }

    // --- scan ---
    __shared__ int wsum[32];
    __shared__ int wsum2[4];
    __shared__ bool s_last;
    int i = blockIdx.x * SCAN_B + t;
    int v = (i < n_nodes) ? g_cnt[i] : 0;

    int x = v;
    #pragma unroll
    for (int o = 1; o < 32; o <<= 1) {
        int y = __shfl_up_sync(0xFFFFFFFFu, x, o);
        if (lane >= o) x += y;
    }
    if (lane == 31) wsum[wid] = x;
    __syncthreads();
    if (wid == 0) {
        int s = wsum[lane];
        #pragma unroll
        for (int o = 1; o < 32; o <<= 1) {
            int y = __shfl_up_sync(0xFFFFFFFFu, s, o);
            if (lane >= o) s += y;
        }
        wsum[lane] = s;
    }
    __syncthreads();
    int incl = x + (wid ? wsum[wid - 1] : 0);
    if (i < n_nodes) g_rowstart[i] = incl - v;
    if (t == SCAN_B - 1) g_bsum[blockIdx.x] = incl;

    __threadfence();
    if (t == 0)
        s_last = (atomicAdd(&g_scan_done, 1) == scan_blocks - 1);
    __syncthreads();

    if (s_last) {
        int bv = 0, bx = 0;
        if (t < MAXBLK) {
            bv = (t < scan_blocks) ? g_bsum[t] : 0;
            bx = bv;
            #pragma unroll
            for (int o = 1; o < 32; o <<= 1) {
                int y = __shfl_up_sync(0xFFFFFFFFu, bx, o);
                if (lane >= o) bx += y;
            }
            if (lane == 31) wsum2[wid] = bx;
        }
        __syncthreads();
        if (t < MAXBLK) {
            int pre = 0;
            #pragma unroll
            for (int w = 0; w < 4; ++w) if (w < wid) pre += wsum2[w];
            g_bpref[t] = bx + pre - bv;
        }
    }
}

// ---------------------------------------------------------------------------
// k3: scatter blocks [0, scatter_blocks) + LN chunk blocks after.
// scatter: atomic-free (rank-based); threads 0..n_nodes also materialize
// ABSOLUTE rowstarts into g_rowabs (g_rowabs[n_nodes] = n_edges).
// ---------------------------------------------------------------------------
__global__ void __launch_bounds__(SCAN_B)
scatter_ln_kernel(const int* __restrict__ row,
                  const int* __restrict__ col,
                  const float* __restrict__ val,
                  const float* __restrict__ ln_in, float* __restrict__ ln_out,
                  int n_edges, int n_nodes, int scatter_blocks, int ln_node_base) {
    int t = threadIdx.x, lane = t & 31, wid = t >> 5;

    if (blockIdx.x >= scatter_blocks) {
        // --- LN chunk ---
        int node = ln_node_base + (blockIdx.x - scatter_blocks) * (SCAN_B / 32) + wid;
        if (node < n_nodes) ln_node(ln_in, ln_out, node, lane);
        return;
    }

    int e = blockIdx.x * SCAN_B + t;

    // absolute rowstart fixup (first n_nodes+1 threads)
    if (e <= n_nodes)
        g_rowabs[e] = (e < n_nodes) ? (g_rowstart[e] + g_bpref[e >> 10]) : n_edges;

    if (e >= n_edges) return;

    int   r  = __ldg(row + e);      // independent loads up front
    int   c  = __ldg(col + e);
    float v  = __ldg(val + e);
    int   rk = __ldg(&g_rank[e]);

    int base = __ldg(&g_rowstart[r]) + __ldg(&g_bpref[r >> 10]);
    g_edges[base + rk] = make_uint2((unsigned)c, __float_as_uint(v));
}

// ---------------------------------------------------------------------------
// SpMM (round-4 proven structure): 1 warp per row, lane owns one float4.
// Prologue now: two independent 4B loads from g_rowabs (absolute starts).
// FINAL==0 : y = acc                    (layers 1,2 — zero `out` traffic)
// FINAL==1 : out = acc + y1[r] + x[r]   (layer 3; x row == y2; streaming hints)
// ---------------------------------------------------------------------------
template <int FINAL>
__global__ void __launch_bounds__(256)
spmm_kernel(const float* __restrict__ x,
            float* __restrict__ y,
            const float* __restrict__ y1,
            float* __restrict__ out,
            int n_nodes) {
    int r = (blockIdx.x * blockDim.x + threadIdx.x) >> 5;
    if (r >= n_nodes) return;
    int lane = threadIdx.x & 31;

    int base = __ldg(&g_rowabs[r]);
    int deg  = __ldg(&g_rowabs[r + 1]) - base;

    const float4* x4 = reinterpret_cast<const float4*>(x);
    float4 acc = make_float4(0.f, 0.f, 0.f, 0.f);

    for (int s = 0; s < deg; s += 32) {
        int m = deg - s; if (m > 32) m = 32;
        uint2 ev = make_uint2(0u, 0u);
        if (lane < m) ev = __ldg(&g_edges[base + s + lane]);   // coalesced meta
        #pragma unroll 4
        for (int k = 0; k < m; ++k) {
            int   c = __shfl_sync(0xFFFFFFFFu, (int)ev.x, k);
            float v = __uint_as_float(__shfl_sync(0xFFFFFFFFu, (int)ev.y, k));
            float4 xv = __ldg(x4 + (size_t)c * VEC + lane);
            acc.x = fmaf(v, xv.x, acc.x);
            acc.y = fmaf(v, xv.y, acc.y);
            acc.z = fmaf(v, xv.z, acc.z);
            acc.w = fmaf(v, xv.w, acc.w);
        }
    }

    size_t oi = (size_t)r * VEC + lane;
    if (FINAL == 0) {
        reinterpret_cast<float4*>(y)[oi] = acc;   // stays L2-hot for next layer
    } else {
        float4 a = __ldcs(reinterpret_cast<const float4*>(y1) + oi);  // evict-first
        float4 b = __ldg(x4 + oi);                                    // y2 row: L2-hot
        acc.x += a.x + b.x; acc.y += a.y + b.y;
        acc.z += a.z + b.z; acc.w += a.w + b.w;
        __stcs(reinterpret_cast<float4*>(out) + oi, acc);             // streaming
    }
}

// ---------------------------------------------------------------------------
// Launcher
// ---------------------------------------------------------------------------
extern "C" void kernel_launch(void* const* d_in, const int* in_sizes, int n_in,
                              void* d_out, int out_size) {
    const float* embeds  = (const float*)d_in[0];
    const int*   adj_row = (const int*)d_in[1];
    const int*   adj_col = (const int*)d_in[2];
    const float* adj_val = (const float*)d_in[3];

    int n_nodes = in_sizes[0] / LATDIM;
    int n_edges = in_sizes[1];

    float* bufA = nullptr;
    float* bufB = nullptr;
    cudaGetSymbolAddress((void**)&bufA, g_bufA);
    cudaGetSymbolAddress((void**)&bufB, g_bufB);
    float* out = (float*)d_out;

    const int TPB = 256;
    int warp_blocks    = (n_nodes * 32 + TPB - 1) / TPB;       // spmm: 1 warp/node
    int scan_blocks    = (n_nodes + SCAN_B - 1) / SCAN_B;      // 98
    int edge_blocks256 = (n_edges + TPB - 1) / TPB;            // hist
    int scatter_blocks = (n_edges + SCAN_B - 1) / SCAN_B;      // 625

    // LN split: ~35% co-scheduled with scan, rest with scatter
    int nodes_per_blk = SCAN_B / 32;                           // 32 nodes/block
    int ln1_nodes  = (int)((long long)n_nodes * 35 / 100);
    int ln1_blocks = (ln1_nodes + nodes_per_blk - 1) / nodes_per_blk;
    ln1_nodes = ln1_blocks * nodes_per_blk;                    // round to blocks
    if (ln1_nodes > n_nodes) ln1_nodes = n_nodes;
    int ln2_nodes  = n_nodes - ln1_nodes;
    int ln2_blocks = (ln2_nodes + nodes_per_blk - 1) / nodes_per_blk;

    // 1) zero counters + election reset
    zero_kernel<<<(n_nodes + SCAN_B - 1) / SCAN_B, SCAN_B>>>(n_nodes);
    // 2) degree histogram + within-row ranks
    hist_kernel<<<edge_blocks256, TPB>>>(adj_row, n_edges);
    // 3) scan  ∥  LN part 1   (embeds -> bufA nodes [0, ln1))
    scan_ln_kernel<<<scan_blocks + ln1_blocks, SCAN_B>>>(
        embeds, bufA, n_nodes, scan_blocks, 0);
    // 4) scatter + rowabs fixup  ∥  LN part 2  (nodes [ln1, n))
    scatter_ln_kernel<<<scatter_blocks + ln2_blocks, SCAN_B>>>(
        adj_row, adj_col, adj_val, embeds, bufA,
        n_edges, n_nodes, scatter_blocks, ln1_nodes);

    // 5) Layer 1: y1 = A * x0          (bufA -> bufB)
    spmm_kernel<0><<<warp_blocks, TPB>>>(bufA, bufB, nullptr, nullptr, n_nodes);
    // 6) Layer 2: y2 = A * y1          (bufB -> bufA)
    spmm_kernel<0><<<warp_blocks, TPB>>>(bufB, bufA, nullptr, nullptr, n_nodes);
    // 7) Layer 3: out = A*y2 + y1 + y2 (gather bufA; add bufB + bufA rows)
    spmm_kernel<1><<<warp_blocks, TPB>>>(bufA, nullptr, bufB, out, n_nodes);
}

// round 12
// speedup vs baseline: 1.6544x; 1.0099x over previous
#include <cuda_runtime.h>
#include <cuda_bf16.h>

#define NMAX   100000
#define EMAX   640000
#define LATDIM 128
#define VEC    32          // float4 per row
#define SCAN_B 1024
#define MAXBLK 128         // >= number of scan blocks (98)

// ---- scratch (__device__ globals; zero-initialized at module load) ---------
__device__ float g_bufA[(size_t)NMAX * LATDIM];
__device__ float g_bufB[(size_t)NMAX * LATDIM];
__device__ int   g_cnt[NMAX];          // per-row degree (zero at entry, re-zeroed by scatter)
__device__ int   g_rowstart[NMAX];     // block-local exclusive scan
__device__ int   g_rowabs[NMAX + 1];   // ABSOLUTE row starts
__device__ int   g_bsum[MAXBLK];       // per-scan-block totals
__device__ int   g_bpref[MAXBLK];      // exclusive scan of totals
__device__ int   g_rank[EMAX];         // within-row rank of each edge
__device__ uint2 g_edges[EMAX];        // row-sorted {col, val bits}
__device__ int   g_scan_done;          // scan election counter (reset by scatter)

// ---------------------------------------------------------------------------
// LN body: one warp per node (1024-thread blocks => 32 nodes/block)
// ---------------------------------------------------------------------------
__device__ __forceinline__ void ln_node(const float* __restrict__ in,
                                        float* __restrict__ out,
                                        int node, int lane) {
    float4 v = __ldg(reinterpret_cast<const float4*>(in) + (size_t)node * VEC + lane);

    float s  = v.x + v.y + v.z + v.w;
    float ss = v.x * v.x + v.y * v.y + v.z * v.z + v.w * v.w;
    #pragma unroll
    for (int o = 16; o > 0; o >>= 1) {
        s  += __shfl_xor_sync(0xFFFFFFFFu, s,  o);
        ss += __shfl_xor_sync(0xFFFFFFFFu, ss, o);
    }
    float mu  = s * (1.0f / LATDIM);
    float var = ss * (1.0f / LATDIM) - mu * mu;
    float inv = rsqrtf(var + 1e-5f);

    v.x = (v.x - mu) * inv; v.y = (v.y - mu) * inv;
    v.z = (v.z - mu) * inv; v.w = (v.w - mu) * inv;

    reinterpret_cast<float4*>(out)[(size_t)node * VEC + lane] = v;
}

// ---------------------------------------------------------------------------
// k1: hist blocks [0, hist_blocks) + LN chunk blocks after.
// hist: one edge/thread; atomic return value IS the within-row rank.
// Requires g_cnt == 0 at kernel entry (module init / recycled by scatter).
// ---------------------------------------------------------------------------
__global__ void __launch_bounds__(SCAN_B)
hist_ln_kernel(const int* __restrict__ row,
               const float* __restrict__ ln_in, float* __restrict__ ln_out,
               int n_edges, int n_nodes, int hist_blocks, int ln_node_base) {
    int t = threadIdx.x, lane = t & 31, wid = t >> 5;

    if (blockIdx.x >= hist_blocks) {
        int node = ln_node_base + (blockIdx.x - hist_blocks) * (SCAN_B / 32) + wid;
        if (node < n_nodes) ln_node(ln_in, ln_out, node, lane);
        return;
    }

    int e = blockIdx.x * SCAN_B + t;
    if (e < n_edges)
        g_rank[e] = atomicAdd(&g_cnt[row[e]], 1);
}

// ---------------------------------------------------------------------------
// k2: scan blocks [0, scan_blocks) + LN chunk blocks after.
// ---------------------------------------------------------------------------
__global__ void __launch_bounds__(SCAN_B)
scan_ln_kernel(const float* __restrict__ ln_in, float* __restrict__ ln_out,
               int n_nodes, int scan_blocks, int ln_node_base) {
    int t = threadIdx.x, lane = t & 31, wid = t >> 5;

    if (blockIdx.x >= scan_blocks) {
        int node = ln_node_base + (blockIdx.x - scan_blocks) * (SCAN_B / 32) + wid;
        if (node < n_nodes) ln_node(ln_in, ln_out, node, lane);
        return;
    }

    __shared__ int wsum[32];
    __shared__ int wsum2[4];
    __shared__ bool s_last;
    int i = blockIdx.x * SCAN_B + t;
    int v = (i < n_nodes) ? g_cnt[i] : 0;

    int x = v;
    #pragma unroll
    for (int o = 1; o < 32; o <<= 1) {
        int y = __shfl_up_sync(0xFFFFFFFFu, x, o);
        if (lane >= o) x += y;
    }
    if (lane == 31) wsum[wid] = x;
    __syncthreads();
    if (wid == 0) {
        int s = wsum[lane];
        #pragma unroll
        for (int o = 1; o < 32; o <<= 1) {
            int y = __shfl_up_sync(0xFFFFFFFFu, s, o);
            if (lane >= o) s += y;
        }
        wsum[lane] = s;
    }
    __syncthreads();
    int incl = x + (wid ? wsum[wid - 1] : 0);
    if (i < n_nodes) g_rowstart[i] = incl - v;
    if (t == SCAN_B - 1) g_bsum[blockIdx.x] = incl;

    __threadfence();
    if (t == 0)
        s_last = (atomicAdd(&g_scan_done, 1) == scan_blocks - 1);
    __syncthreads();

    if (s_last) {
        int bv = 0, bx = 0;
        if (t < MAXBLK) {
            bv = (t < scan_blocks) ? g_bsum[t] : 0;
            bx = bv;
            #pragma unroll
            for (int o = 1; o < 32; o <<= 1) {
                int y = __shfl_up_sync(0xFFFFFFFFu, bx, o);
                if (lane >= o) bx += y;
            }
            if (lane == 31) wsum2[wid] = bx;
        }
        __syncthreads();
        if (t < MAXBLK) {
            int pre = 0;
            #pragma unroll
            for (int w = 0; w < 4; ++w) if (w < wid) pre += wsum2[w];
            g_bpref[t] = bx + pre - bv;
        }
    }
}

// ---------------------------------------------------------------------------
// k3: scatter blocks [0, scatter_blocks) + LN chunk blocks after.
// scatter: atomic-free (rank-based). First n_nodes+1 threads also:
//   - materialize ABSOLUTE rowstarts into g_rowabs,
//   - re-zero g_cnt (recycled for the next graph replay),
//   - thread 0 resets g_scan_done.
// ---------------------------------------------------------------------------
__global__ void __launch_bounds__(SCAN_B)
scatter_ln_kernel(const int* __restrict__ row,
                  const int* __restrict__ col,
                  const float* __restrict__ val,
                  const float* __restrict__ ln_in, float* __restrict__ ln_out,
                  int n_edges, int n_nodes, int scatter_blocks, int ln_node_base) {
    int t = threadIdx.x, lane = t & 31, wid = t >> 5;

    if (blockIdx.x >= scatter_blocks) {
        int node = ln_node_base + (blockIdx.x - scatter_blocks) * (SCAN_B / 32) + wid;
        if (node < n_nodes) ln_node(ln_in, ln_out, node, lane);
        return;
    }

    int e = blockIdx.x * SCAN_B + t;

    if (e == 0) g_scan_done = 0;                 // recycle election counter
    if (e <= n_nodes) {
        g_rowabs[e] = (e < n_nodes) ? (g_rowstart[e] + g_bpref[e >> 10]) : n_edges;
        if (e < n_nodes) g_cnt[e] = 0;           // recycle degree counters
    }

    if (e >= n_edges) return;

    int   r  = __ldg(row + e);      // independent loads up front
    int   c  = __ldg(col + e);
    float v  = __ldg(val + e);
    int   rk = __ldg(&g_rank[e]);

    int base = __ldg(&g_rowstart[r]) + __ldg(&g_bpref[r >> 10]);
    g_edges[base + rk] = make_uint2((unsigned)c, __float_as_uint(v));
}

// ---------------------------------------------------------------------------
// SpMM (round-4 proven structure, frozen): 1 warp per row, lane owns one
// float4. Coalesced 32-edge metadata load + shuffle broadcast; register acc.
// FINAL==0 : y = acc                    (layers 1,2 — zero `out` traffic)
// FINAL==1 : out = acc + y1[r] + x[r]   (layer 3; x row == y2; streaming hints)
// ---------------------------------------------------------------------------
template <int FINAL>
__global__ void __launch_bounds__(256)
spmm_kernel(const float* __restrict__ x,
            float* __restrict__ y,
            const float* __restrict__ y1,
            float* __restrict__ out,
            int n_nodes) {
    int r = (blockIdx.x * blockDim.x + threadIdx.x) >> 5;
    if (r >= n_nodes) return;
    int lane = threadIdx.x & 31;

    int base = __ldg(&g_rowabs[r]);
    int deg  = __ldg(&g_rowabs[r + 1]) - base;

    const float4* x4 = reinterpret_cast<const float4*>(x);
    float4 acc = make_float4(0.f, 0.f, 0.f, 0.f);

    for (int s = 0; s < deg; s += 32) {
        int m = deg - s; if (m > 32) m = 32;
        uint2 ev = make_uint2(0u, 0u);
        if (lane < m) ev = __ldg(&g_edges[base + s + lane]);   // coalesced meta
        #pragma unroll 4
        for (int k = 0; k < m; ++k) {
            int   c = __shfl_sync(0xFFFFFFFFu, (int)ev.x, k);
            float v = __uint_as_float(__shfl_sync(0xFFFFFFFFu, (int)ev.y, k));
            float4 xv = __ldg(x4 + (size_t)c * VEC + lane);
            acc.x = fmaf(v, xv.x, acc.x);
            acc.y = fmaf(v, xv.y, acc.y);
            acc.z = fmaf(v, xv.z, acc.z);
            acc.w = fmaf(v, xv.w, acc.w);
        }
    }

    size_t oi = (size_t)r * VEC + lane;
    if (FINAL == 0) {
        reinterpret_cast<float4*>(y)[oi] = acc;   // stays L2-hot for next layer
    } else {
        float4 a = __ldcs(reinterpret_cast<const float4*>(y1) + oi);  // evict-first
        float4 b = __ldg(x4 + oi);                                    // y2 row: L2-hot
        acc.x += a.x + b.x; acc.y += a.y + b.y;
        acc.z += a.z + b.z; acc.w += a.w + b.w;
        __stcs(reinterpret_cast<float4*>(out) + oi, acc);             // streaming
    }
}

// ---------------------------------------------------------------------------
// Launcher
// ---------------------------------------------------------------------------
extern "C" void kernel_launch(void* const* d_in, const int* in_sizes, int n_in,
                              void* d_out, int out_size) {
    const float* embeds  = (const float*)d_in[0];
    const int*   adj_row = (const int*)d_in[1];
    const int*   adj_col = (const int*)d_in[2];
    const float* adj_val = (const float*)d_in[3];

    int n_nodes = in_sizes[0] / LATDIM;
    int n_edges = in_sizes[1];

    float* bufA = nullptr;
    float* bufB = nullptr;
    cudaGetSymbolAddress((void**)&bufA, g_bufA);
    cudaGetSymbolAddress((void**)&bufB, g_bufB);
    float* out = (float*)d_out;

    const int TPB = 256;
    int warp_blocks    = (n_nodes * 32 + TPB - 1) / TPB;       // spmm: 1 warp/node
    int scan_blocks    = (n_nodes + SCAN_B - 1) / SCAN_B;      // 98
    int hist_blocks    = (n_edges + SCAN_B - 1) / SCAN_B;      // 625
    int scatter_blocks = (n_edges + SCAN_B - 1) / SCAN_B;      // 625

    // LN split across the three build kernels, ~proportional to their durations
    int nodes_per_blk = SCAN_B / 32;                           // 32 nodes/block
    int ln0_nodes = (int)((long long)n_nodes * 30 / 100);      // with hist
    int ln1_nodes = (int)((long long)n_nodes * 20 / 100);      // with scan
    int ln0_blocks = (ln0_nodes + nodes_per_blk - 1) / nodes_per_blk;
    ln0_nodes = ln0_blocks * nodes_per_blk;
    int ln1_blocks = (ln1_nodes + nodes_per_blk - 1) / nodes_per_blk;
    ln1_nodes = ln1_blocks * nodes_per_blk;
    if (ln0_nodes + ln1_nodes > n_nodes) { ln1_nodes = n_nodes - ln0_nodes; ln1_blocks = (ln1_nodes + nodes_per_blk - 1) / nodes_per_blk; }
    int ln2_base   = ln0_nodes + ln1_nodes;                    // with scatter
    int ln2_nodes  = n_nodes - ln2_base;
    int ln2_blocks = (ln2_nodes + nodes_per_blk - 1) / nodes_per_blk;

    // 1) hist  ∥  LN part 0      (g_cnt arrives zeroed — module init / recycled)
    hist_ln_kernel<<<hist_blocks + ln0_blocks, SCAN_B>>>(
        adj_row, embeds, bufA, n_edges, n_nodes, hist_blocks, 0);
    // 2) scan  ∥  LN part 1
    scan_ln_kernel<<<scan_blocks + ln1_blocks, SCAN_B>>>(
        embeds, bufA, n_nodes, scan_blocks, ln0_nodes);
    // 3) scatter + rowabs fixup + counter recycle  ∥  LN part 2
    scatter_ln_kernel<<<scatter_blocks + ln2_blocks, SCAN_B>>>(
        adj_row, adj_col, adj_val, embeds, bufA,
        n_edges, n_nodes, scatter_blocks, ln2_base);

    // 4) Layer 1: y1 = A * x0          (bufA -> bufB)
    spmm_kernel<0><<<warp_blocks, TPB>>>(bufA, bufB, nullptr, nullptr, n_nodes);
    // 5) Layer 2: y2 = A * y1          (bufB -> bufA)
    spmm_kernel<0><<<warp_blocks, TPB>>>(bufB, bufA, nullptr, nullptr, n_nodes);
    // 6) Layer 3: out = A*y2 + y1 + y2 (gather bufA; add bufB + bufA rows)
    spmm_kernel<1><<<warp_blocks, TPB>>>(bufA, nullptr, bufB, out, n_nodes);
}

// round 13
// speedup vs baseline: 1.7214x; 1.0405x over previous
#include <cuda_runtime.h>
#include <cuda_bf16.h>

#define NMAX   100000
#define EMAX   640000
#define LATDIM 128
#define VEC    32          // float4 per row
#define SCAN_B 1024
#define MAXBLK 128         // >= number of scan blocks (98)
#define SPMM_TPB 128       // small blocks: fine-grain retire + phase diversity

// ---- scratch (__device__ globals; zero-initialized at module load) ---------
__device__ float g_bufA[(size_t)NMAX * LATDIM];
__device__ float g_bufB[(size_t)NMAX * LATDIM];
__device__ int   g_cnt[NMAX];          // per-row degree (zero at entry, re-zeroed by scatter)
__device__ int   g_rowstart[NMAX];     // block-local exclusive scan
__device__ int   g_rowabs[NMAX + 1];   // ABSOLUTE row starts
__device__ int   g_bsum[MAXBLK];       // per-scan-block totals
__device__ int   g_bpref[MAXBLK];      // exclusive scan of totals
__device__ int   g_rank[EMAX];         // within-row rank of each edge
__device__ uint2 g_edges[EMAX];        // row-sorted {col, val bits}
__device__ int   g_scan_done;          // scan election counter (reset by scatter)

// ---------------------------------------------------------------------------
// LN body: one warp per node (1024-thread blocks => 32 nodes/block)
// ---------------------------------------------------------------------------
__device__ __forceinline__ void ln_node(const float* __restrict__ in,
                                        float* __restrict__ out,
                                        int node, int lane) {
    float4 v = __ldg(reinterpret_cast<const float4*>(in) + (size_t)node * VEC + lane);

    float s  = v.x + v.y + v.z + v.w;
    float ss = v.x * v.x + v.y * v.y + v.z * v.z + v.w * v.w;
    #pragma unroll
    for (int o = 16; o > 0; o >>= 1) {
        s  += __shfl_xor_sync(0xFFFFFFFFu, s,  o);
        ss += __shfl_xor_sync(0xFFFFFFFFu, ss, o);
    }
    float mu  = s * (1.0f / LATDIM);
    float var = ss * (1.0f / LATDIM) - mu * mu;
    float inv = rsqrtf(var + 1e-5f);

    v.x = (v.x - mu) * inv; v.y = (v.y - mu) * inv;
    v.z = (v.z - mu) * inv; v.w = (v.w - mu) * inv;

    reinterpret_cast<float4*>(out)[(size_t)node * VEC + lane] = v;
}

// ---------------------------------------------------------------------------
// k1: hist blocks [0, hist_blocks) + LN chunk blocks after.
// ---------------------------------------------------------------------------
__global__ void __launch_bounds__(SCAN_B)
hist_ln_kernel(const int* __restrict__ row,
               const float* __restrict__ ln_in, float* __restrict__ ln_out,
               int n_edges, int n_nodes, int hist_blocks, int ln_node_base) {
    int t = threadIdx.x, lane = t & 31, wid = t >> 5;

    if (blockIdx.x >= hist_blocks) {
        int node = ln_node_base + (blockIdx.x - hist_blocks) * (SCAN_B / 32) + wid;
        if (node < n_nodes) ln_node(ln_in, ln_out, node, lane);
        return;
    }

    int e = blockIdx.x * SCAN_B + t;
    if (e < n_edges)
        g_rank[e] = atomicAdd(&g_cnt[row[e]], 1);
}

// ---------------------------------------------------------------------------
// k2: scan blocks [0, scan_blocks) + LN chunk blocks after.
// ---------------------------------------------------------------------------
__global__ void __launch_bounds__(SCAN_B)
scan_ln_kernel(const float* __restrict__ ln_in, float* __restrict__ ln_out,
               int n_nodes, int scan_blocks, int ln_node_base) {
    int t = threadIdx.x, lane = t & 31, wid = t >> 5;

    if (blockIdx.x >= scan_blocks) {
        int node = ln_node_base + (blockIdx.x - scan_blocks) * (SCAN_B / 32) + wid;
        if (node < n_nodes) ln_node(ln_in, ln_out, node, lane);
        return;
    }

    __shared__ int wsum[32];
    __shared__ int wsum2[4];
    __shared__ bool s_last;
    int i = blockIdx.x * SCAN_B + t;
    int v = (i < n_nodes) ? g_cnt[i] : 0;

    int x = v;
    #pragma unroll
    for (int o = 1; o < 32; o <<= 1) {
        int y = __shfl_up_sync(0xFFFFFFFFu, x, o);
        if (lane >= o) x += y;
    }
    if (lane == 31) wsum[wid] = x;
    __syncthreads();
    if (wid == 0) {
        int s = wsum[lane];
        #pragma unroll
        for (int o = 1; o < 32; o <<= 1) {
            int y = __shfl_up_sync(0xFFFFFFFFu, s, o);
            if (lane >= o) s += y;
        }
        wsum[lane] = s;
    }
    __syncthreads();
    int incl = x + (wid ? wsum[wid - 1] : 0);
    if (i < n_nodes) g_rowstart[i] = incl - v;
    if (t == SCAN_B - 1) g_bsum[blockIdx.x] = incl;

    __threadfence();
    if (t == 0)
        s_last = (atomicAdd(&g_scan_done, 1) == scan_blocks - 1);
    __syncthreads();

    if (s_last) {
        int bv = 0, bx = 0;
        if (t < MAXBLK) {
            bv = (t < scan_blocks) ? g_bsum[t] : 0;
            bx = bv;
            #pragma unroll
            for (int o = 1; o < 32; o <<= 1) {
                int y = __shfl_up_sync(0xFFFFFFFFu, bx, o);
                if (lane >= o) bx += y;
            }
            if (lane == 31) wsum2[wid] = bx;
        }
        __syncthreads();
        if (t < MAXBLK) {
            int pre = 0;
            #pragma unroll
            for (int w = 0; w < 4; ++w) if (w < wid) pre += wsum2[w];
            g_bpref[t] = bx + pre - bv;
        }
    }
}

// ---------------------------------------------------------------------------
// k3: scatter blocks [0, scatter_blocks) + LN chunk blocks after.
// scatter: atomic-free (rank-based). First n_nodes+1 threads also:
//   - materialize ABSOLUTE rowstarts into g_rowabs,
//   - re-zero g_cnt, reset g_scan_done (recycled for next graph replay).
// ---------------------------------------------------------------------------
__global__ void __launch_bounds__(SCAN_B)
scatter_ln_kernel(const int* __restrict__ row,
                  const int* __restrict__ col,
                  const float* __restrict__ val,
                  const float* __restrict__ ln_in, float* __restrict__ ln_out,
                  int n_edges, int n_nodes, int scatter_blocks, int ln_node_base) {
    int t = threadIdx.x, lane = t & 31, wid = t >> 5;

    if (blockIdx.x >= scatter_blocks) {
        int node = ln_node_base + (blockIdx.x - scatter_blocks) * (SCAN_B / 32) + wid;
        if (node < n_nodes) ln_node(ln_in, ln_out, node, lane);
        return;
    }

    int e = blockIdx.x * SCAN_B + t;

    if (e == 0) g_scan_done = 0;                 // recycle election counter
    if (e <= n_nodes) {
        g_rowabs[e] = (e < n_nodes) ? (g_rowstart[e] + g_bpref[e >> 10]) : n_edges;
        if (e < n_nodes) g_cnt[e] = 0;           // recycle degree counters
    }

    if (e >= n_edges) return;

    int   r  = __ldg(row + e);      // independent loads up front
    int   c  = __ldg(col + e);
    float v  = __ldg(val + e);
    int   rk = __ldg(&g_rank[e]);

    int base = __ldg(&g_rowstart[r]) + __ldg(&g_bpref[r >> 10]);
    g_edges[base + rk] = make_uint2((unsigned)c, __float_as_uint(v));
}

// ---------------------------------------------------------------------------
// SpMM (round-4 proven inner structure, frozen): 1 warp per row, lane owns
// one float4. NOW 128-thread blocks: finer retirement granularity under
// degree skew + phase-diverse warps per SMSP (latency-bound fix).
// FINAL==0 : y = acc                    (layers 1,2 — zero `out` traffic)
// FINAL==1 : out = acc + y1[r] + x[r]   (layer 3; x row == y2; streaming hints)
// ---------------------------------------------------------------------------
template <int FINAL>
__global__ void __launch_bounds__(SPMM_TPB)
spmm_kernel(const float* __restrict__ x,
            float* __restrict__ y,
            const float* __restrict__ y1,
            float* __restrict__ out,
            int n_nodes) {
    int r = (blockIdx.x * blockDim.x + threadIdx.x) >> 5;
    if (r >= n_nodes) return;
    int lane = threadIdx.x & 31;

    int base = __ldg(&g_rowabs[r]);
    int deg  = __ldg(&g_rowabs[r + 1]) - base;

    const float4* x4 = reinterpret_cast<const float4*>(x);
    float4 acc = make_float4(0.f, 0.f, 0.f, 0.f);

    for (int s = 0; s < deg; s += 32) {
        int m = deg - s; if (m > 32) m = 32;
        uint2 ev = make_uint2(0u, 0u);
        if (lane < m) ev = __ldg(&g_edges[base + s + lane]);   // coalesced meta
        #pragma unroll 4
        for (int k = 0; k < m; ++k) {
            int   c = __shfl_sync(0xFFFFFFFFu, (int)ev.x, k);
            float v = __uint_as_float(__shfl_sync(0xFFFFFFFFu, (int)ev.y, k));
            float4 xv = __ldg(x4 + (size_t)c * VEC + lane);
            acc.x = fmaf(v, xv.x, acc.x);
            acc.y = fmaf(v, xv.y, acc.y);
            acc.z = fmaf(v, xv.z, acc.z);
            acc.w = fmaf(v, xv.w, acc.w);
        }
    }

    size_t oi = (size_t)r * VEC + lane;
    if (FINAL == 0) {
        reinterpret_cast<float4*>(y)[oi] = acc;   // stays L2-hot for next layer
    } else {
        float4 a = __ldcs(reinterpret_cast<const float4*>(y1) + oi);  // evict-first
        float4 b = __ldg(x4 + oi);                                    // y2 row: L2-hot
        acc.x += a.x + b.x; acc.y += a.y + b.y;
        acc.z += a.z + b.z; acc.w += a.w + b.w;
        __stcs(reinterpret_cast<float4*>(out) + oi, acc);             // streaming
    }
}

// ---------------------------------------------------------------------------
// Launcher
// ---------------------------------------------------------------------------
extern "C" void kernel_launch(void* const* d_in, const int* in_sizes, int n_in,
                              void* d_out, int out_size) {
    const float* embeds  = (const float*)d_in[0];
    const int*   adj_row = (const int*)d_in[1];
    const int*   adj_col = (const int*)d_in[2];
    const float* adj_val = (const float*)d_in[3];

    int n_nodes = in_sizes[0] / LATDIM;
    int n_edges = in_sizes[1];

    float* bufA = nullptr;
    float* bufB = nullptr;
    cudaGetSymbolAddress((void**)&bufA, g_bufA);
    cudaGetSymbolAddress((void**)&bufB, g_bufB);
    float* out = (float*)d_out;

    int spmm_blocks    = (n_nodes * 32 + SPMM_TPB - 1) / SPMM_TPB;  // 1 warp/node
    int scan_blocks    = (n_nodes + SCAN_B - 1) / SCAN_B;           // 98
    int hist_blocks    = (n_edges + SCAN_B - 1) / SCAN_B;           // 625
    int scatter_blocks = (n_edges + SCAN_B - 1) / SCAN_B;           // 625

    // LN split across the three build kernels (~proportional to durations)
    int nodes_per_blk = SCAN_B / 32;                                // 32 nodes/block
    int ln0_nodes = (int)((long long)n_nodes * 30 / 100);           // with hist
    int ln1_nodes = (int)((long long)n_nodes * 20 / 100);           // with scan
    int ln0_blocks = (ln0_nodes + nodes_per_blk - 1) / nodes_per_blk;
    ln0_nodes = ln0_blocks * nodes_per_blk;
    int ln1_blocks = (ln1_nodes + nodes_per_blk - 1) / nodes_per_blk;
    ln1_nodes = ln1_blocks * nodes_per_blk;
    if (ln0_nodes + ln1_nodes > n_nodes) {
        ln1_nodes  = n_nodes - ln0_nodes;
        ln1_blocks = (ln1_nodes + nodes_per_blk - 1) / nodes_per_blk;
    }
    int ln2_base   = ln0_nodes + ln1_nodes;                         // with scatter
    int ln2_nodes  = n_nodes - ln2_base;
    int ln2_blocks = (ln2_nodes + nodes_per_blk - 1) / nodes_per_blk;

    // 1) hist  ∥  LN part 0   (g_cnt arrives zeroed — module init / recycled)
    hist_ln_kernel<<<hist_blocks + ln0_blocks, SCAN_B>>>(
        adj_row, embeds, bufA, n_edges, n_nodes, hist_blocks, 0);
    // 2) scan  ∥  LN part 1
    scan_ln_kernel<<<scan_blocks + ln1_blocks, SCAN_B>>>(
        embeds, bufA, n_nodes, scan_blocks, ln0_nodes);
    // 3) scatter + rowabs fixup + counter recycle  ∥  LN part 2
    scatter_ln_kernel<<<scatter_blocks + ln2_blocks, SCAN_B>>>(
        adj_row, adj_col, adj_val, embeds, bufA,
        n_edges, n_nodes, scatter_blocks, ln2_base);

    // 4) Layer 1: y1 = A * x0          (bufA -> bufB)
    spmm_kernel<0><<<spmm_blocks, SPMM_TPB>>>(bufA, bufB, nullptr, nullptr, n_nodes);
    // 5) Layer 2: y2 = A * y1          (bufB -> bufA)
    spmm_kernel<0><<<spmm_blocks, SPMM_TPB>>>(bufB, bufA, nullptr, nullptr, n_nodes);
    // 6) Layer 3: out = A*y2 + y1 + y2 (gather bufA; add bufB + bufA rows)
    spmm_kernel<1><<<spmm_blocks, SPMM_TPB>>>(bufA, nullptr, bufB, out, n_nodes);
}